// round 11
// baseline (speedup 1.0000x reference)
#include <cuda_runtime.h>
#include <cuda_bf16.h>

// RobustSum L1 IRLS (K=3): x(128,1024) @ W(1024,1024) -> z(128,1024), fp32.
//
// Per (b,o): c = z/D1; t_i = x_i*W_io - c; r_i = 1/(|t_i|+eps);
// q = sum r_i t_i, sw = sum r_i; c' = (q + c*sw)/max(sw,1e-12); out = D1*c.
// Pairing (exact): with d = |t|+eps,
//   r_i + r_j       = (d_i+d_j) * rcp(d_i*d_j)
//   r_i t_i+r_j t_j = (t_i d_j + t_j d_i) * rcp(d_i*d_j)
//
// R11 = pairing (R10) x b-reuse (R6): thread = 4b x 2o x paired-i.
// One LDG.64 (2 o-weights) + one LDS.128 (x4 interleaved {b0..b3}) per i
// serve 8 lane-elements; per warp 2i-step covers 512 lane-el in ~66 instrs
// (0.129 instr/lane-el, best so far). Block = 256 thr = 8 warps = 8 i-chunks
// of 128; block = 4b x 64o; grid (16,32) = 512 blocks = one wave at 4 CTA/SM.

#define DIN     1024
#define DOUT    1024
#define KITER   3
#define EPSILON 0.001f
#define ICHUNK  128
#define NTHREADS 256

typedef unsigned long long ull;

__device__ __forceinline__ ull pack2(float lo, float hi) {
    ull r; asm("mov.b64 %0, {%1,%2};" : "=l"(r) : "f"(lo), "f"(hi)); return r;
}
__device__ __forceinline__ void unpack2(ull v, float& lo, float& hi) {
    asm("mov.b64 {%0,%1}, %2;" : "=f"(lo), "=f"(hi) : "l"(v));
}
__device__ __forceinline__ ull fma2(ull a, ull b, ull c) {
    ull r; asm("fma.rn.f32x2 %0, %1, %2, %3;" : "=l"(r) : "l"(a), "l"(b), "l"(c)); return r;
}
__device__ __forceinline__ ull add2(ull a, ull b) {
    ull r; asm("add.rn.f32x2 %0, %1, %2;" : "=l"(r) : "l"(a), "l"(b)); return r;
}
__device__ __forceinline__ ull mul2(ull a, ull b) {
    ull r; asm("mul.rn.f32x2 %0, %1, %2;" : "=l"(r) : "l"(a), "l"(b)); return r;
}
__device__ __forceinline__ float rcpf(float a) {
    float r; asm("rcp.approx.f32 %0, %1;" : "=f"(r) : "f"(a)); return r;
}
__device__ __forceinline__ ull rcp2(ull m) {
    float a, b; unpack2(m, a, b);
    return pack2(rcpf(a), rcpf(b));
}

#define ABSM 0x7FFFFFFF7FFFFFFFULL

__global__ __launch_bounds__(NTHREADS, 4)
void robust_sum_kernel(const float* __restrict__ x,
                       const float* __restrict__ w,
                       float* __restrict__ out)
{
    __shared__ float4 xs4[DIN];            // 16 KB: {x[b0][i],x[b1][i],x[b2][i],x[b3][i]}
    __shared__ ull red[8][32][8];          // 16 KB: [iq][lane][4b x {q,sw}]

    const int tid  = threadIdx.x;
    const int iq   = tid >> 5;             // warp == i-chunk 0..7 (128 i each)
    const int lane = tid & 31;
    const int o0   = blockIdx.x * 64 + lane * 2;
    const int b0   = blockIdx.y * 4;

    // Stage x interleaved 4-wide (one-time, 4 KB of source).
    for (int t = tid; t < DIN; t += NTHREADS) {
        xs4[t] = make_float4(x[(size_t)(b0 + 0) * DIN + t],
                             x[(size_t)(b0 + 1) * DIN + t],
                             x[(size_t)(b0 + 2) * DIN + t],
                             x[(size_t)(b0 + 3) * DIN + t]);
    }
    __syncthreads();

    const float4* xp    = &xs4[iq * ICHUNK];
    const float*  wbase = w + (size_t)(iq * ICHUNK) * DOUT + o0;

    // ---- pass 0: z = x @ W (as c = z/DIN) ----
    ull s0 = 0ULL, s1 = 0ULL, s2 = 0ULL, s3 = 0ULL;   // per-b packed (o0,o1)
    #pragma unroll 4
    for (int i = 0; i < ICHUNK; i++) {
        ull wv = __ldg((const ull*)(wbase + (size_t)i * DOUT));
        float4 xv = xp[i];
        s0 = fma2(pack2(xv.x, xv.x), wv, s0);
        s1 = fma2(pack2(xv.y, xv.y), wv, s1);
        s2 = fma2(pack2(xv.z, xv.z), wv, s2);
        s3 = fma2(pack2(xv.w, xv.w), wv, s3);
    }
    {
        ull* rp = red[iq][lane];
        rp[0] = s0; rp[1] = s1; rp[2] = s2; rp[3] = s3;
    }
    __syncthreads();
    ull c0p, c1p, c2p, c3p;                 // packed c per b: (c_o0, c_o1)
    {
        ull a0 = 0ULL, a1 = 0ULL, a2 = 0ULL, a3 = 0ULL;
        #pragma unroll
        for (int j = 0; j < 8; j++) {
            const ull* rp = red[j][lane];
            a0 = add2(a0, rp[0]);
            a1 = add2(a1, rp[1]);
            a2 = add2(a2, rp[2]);
            a3 = add2(a3, rp[3]);
        }
        const ull inv = pack2(1.0f / DIN, 1.0f / DIN);
        c0p = mul2(a0, inv);
        c1p = mul2(a1, inv);
        c2p = mul2(a2, inv);
        c3p = mul2(a3, inv);
    }

    const ull EPS2 = pack2(EPSILON, EPSILON);
    const ull NEG  = 0x8000000080000000ULL;

    // ---- K IRLS iterations: 4 b's, paired i (1 rcp2 per 2i per b) ----
    #pragma unroll 1
    for (int k = 0; k < KITER; k++) {
        const ull nc0 = c0p ^ NEG;          // -c, packed (alu, cheap)
        const ull nc1 = c1p ^ NEG;
        const ull nc2 = c2p ^ NEG;
        const ull nc3 = c3p ^ NEG;
        ull q0 = 0ULL, q1 = 0ULL, q2 = 0ULL, q3 = 0ULL;
        ull w0 = 0ULL, w1 = 0ULL, w2 = 0ULL, w3 = 0ULL;
        #pragma unroll 2
        for (int i = 0; i < ICHUNK; i += 2) {
            ull wva = __ldg((const ull*)(wbase + (size_t)i * DOUT));
            ull wvb = __ldg((const ull*)(wbase + (size_t)(i + 1) * DOUT));
            float4 xa = xp[i];
            float4 xb = xp[i + 1];
            // per-b pair-combine; 4 independent chains for ILP
            {   // b0
                ull ta = fma2(pack2(xa.x, xa.x), wva, nc0);
                ull tb = fma2(pack2(xb.x, xb.x), wvb, nc0);
                ull da = add2(ta & ABSM, EPS2);
                ull db = add2(tb & ABSM, EPS2);
                ull r  = rcp2(mul2(da, db));
                ull cr = fma2(ta, db, mul2(tb, da));
                q0 = fma2(cr, r, q0);
                w0 = fma2(add2(da, db), r, w0);
            }
            {   // b1
                ull ta = fma2(pack2(xa.y, xa.y), wva, nc1);
                ull tb = fma2(pack2(xb.y, xb.y), wvb, nc1);
                ull da = add2(ta & ABSM, EPS2);
                ull db = add2(tb & ABSM, EPS2);
                ull r  = rcp2(mul2(da, db));
                ull cr = fma2(ta, db, mul2(tb, da));
                q1 = fma2(cr, r, q1);
                w1 = fma2(add2(da, db), r, w1);
            }
            {   // b2
                ull ta = fma2(pack2(xa.z, xa.z), wva, nc2);
                ull tb = fma2(pack2(xb.z, xb.z), wvb, nc2);
                ull da = add2(ta & ABSM, EPS2);
                ull db = add2(tb & ABSM, EPS2);
                ull r  = rcp2(mul2(da, db));
                ull cr = fma2(ta, db, mul2(tb, da));
                q2 = fma2(cr, r, q2);
                w2 = fma2(add2(da, db), r, w2);
            }
            {   // b3
                ull ta = fma2(pack2(xa.w, xa.w), wva, nc3);
                ull tb = fma2(pack2(xb.w, xb.w), wvb, nc3);
                ull da = add2(ta & ABSM, EPS2);
                ull db = add2(tb & ABSM, EPS2);
                ull r  = rcp2(mul2(da, db));
                ull cr = fma2(ta, db, mul2(tb, da));
                q3 = fma2(cr, r, q3);
                w3 = fma2(add2(da, db), r, w3);
            }
        }
        __syncthreads();               // previous reduce reads done
        {
            ull* rp = red[iq][lane];
            rp[0] = q0; rp[1] = q1; rp[2] = q2; rp[3] = q3;
            rp[4] = w0; rp[5] = w1; rp[6] = w2; rp[7] = w3;
        }
        __syncthreads();
        ull qa0 = 0ULL, qa1 = 0ULL, qa2 = 0ULL, qa3 = 0ULL;
        ull wa0 = 0ULL, wa1 = 0ULL, wa2 = 0ULL, wa3 = 0ULL;
        #pragma unroll
        for (int j = 0; j < 8; j++) {
            const ull* rp = red[j][lane];
            qa0 = add2(qa0, rp[0]);
            qa1 = add2(qa1, rp[1]);
            qa2 = add2(qa2, rp[2]);
            qa3 = add2(qa3, rp[3]);
            wa0 = add2(wa0, rp[4]);
            wa1 = add2(wa1, rp[5]);
            wa2 = add2(wa2, rp[6]);
            wa3 = add2(wa3, rp[7]);
        }
        // c' = (q + c*sw)/max(sw,1e-12), per b, scalar epilogue
        float qlo, qhi, wlo, whi, clo, chi;
        unpack2(c0p, clo, chi); unpack2(qa0, qlo, qhi); unpack2(wa0, wlo, whi);
        c0p = pack2(__fdividef(fmaf(clo, wlo, qlo), fmaxf(wlo, 1e-12f)),
                    __fdividef(fmaf(chi, whi, qhi), fmaxf(whi, 1e-12f)));
        unpack2(c1p, clo, chi); unpack2(qa1, qlo, qhi); unpack2(wa1, wlo, whi);
        c1p = pack2(__fdividef(fmaf(clo, wlo, qlo), fmaxf(wlo, 1e-12f)),
                    __fdividef(fmaf(chi, whi, qhi), fmaxf(whi, 1e-12f)));
        unpack2(c2p, clo, chi); unpack2(qa2, qlo, qhi); unpack2(wa2, wlo, whi);
        c2p = pack2(__fdividef(fmaf(clo, wlo, qlo), fmaxf(wlo, 1e-12f)),
                    __fdividef(fmaf(chi, whi, qhi), fmaxf(whi, 1e-12f)));
        unpack2(c3p, clo, chi); unpack2(qa3, qlo, qhi); unpack2(wa3, wlo, whi);
        c3p = pack2(__fdividef(fmaf(clo, wlo, qlo), fmaxf(wlo, 1e-12f)),
                    __fdividef(fmaf(chi, whi, qhi), fmaxf(whi, 1e-12f)));
    }

    if (iq == 0) {
        const float D = (float)DIN;
        float lo, hi;
        unpack2(c0p, lo, hi);
        *(float2*)(out + (size_t)(b0 + 0) * DOUT + o0) = make_float2(D * lo, D * hi);
        unpack2(c1p, lo, hi);
        *(float2*)(out + (size_t)(b0 + 1) * DOUT + o0) = make_float2(D * lo, D * hi);
        unpack2(c2p, lo, hi);
        *(float2*)(out + (size_t)(b0 + 2) * DOUT + o0) = make_float2(D * lo, D * hi);
        unpack2(c3p, lo, hi);
        *(float2*)(out + (size_t)(b0 + 3) * DOUT + o0) = make_float2(D * lo, D * hi);
    }
}

extern "C" void kernel_launch(void* const* d_in, const int* in_sizes, int n_in,
                              void* d_out, int out_size)
{
    const float* x = (const float*)d_in[0];   // (128, 1024)
    const float* w = (const float*)d_in[1];   // (1024, 1024)
    float* out = (float*)d_out;               // (128, 1024)

    dim3 grid(DOUT / 64, 128 / 4);            // (16, 32) = 512 blocks
    robust_sum_kernel<<<grid, NTHREADS>>>(x, w, out);
}

// round 12
// speedup vs baseline: 1.2858x; 1.2858x over previous
#include <cuda_runtime.h>
#include <cuda_bf16.h>

// RobustSum L1 IRLS (K=3): x(128,1024) @ W(1024,1024) -> z(128,1024), fp32.
//
// Per (b,o): c = z/D1; t_i = x_i*W_io - c; r_i = 1/(|t_i|+eps);
// q = sum r_i t_i, sw = sum r_i; c' = (q + c*sw)/max(sw,1e-12); out = D1*c.
// Pairing (exact): with d = |t|+eps,
//   r_i + r_j       = (d_i+d_j) * rcp(d_i*d_j)
//   r_i t_i+r_j t_j = (t_i d_j + t_j d_i) * rcp(d_i*d_j)
//
// R12 = pairing transplanted into R6's winning shape: thread = 2b x 2o,
// i stepped by 2; block = 128 thr = 4 warps (warp = 256-i chunk); block =
// 2b x 64o; grid (16,64) = 1024 blocks; launch_bounds(128,8).
// Only 2 b-chains/thread keeps regs ~55 (R11's 4 chains hit the 64 cap and
// tanked issue). MUFU demand halves vs R6; ~4.6 instr/lane-el vs R6's 6.0.

#define DIN     1024
#define DOUT    1024
#define KITER   3
#define EPSILON 0.001f
#define ICHUNK  256
#define NTHREADS 128

typedef unsigned long long ull;

__device__ __forceinline__ ull pack2(float lo, float hi) {
    ull r; asm("mov.b64 %0, {%1,%2};" : "=l"(r) : "f"(lo), "f"(hi)); return r;
}
__device__ __forceinline__ void unpack2(ull v, float& lo, float& hi) {
    asm("mov.b64 {%0,%1}, %2;" : "=f"(lo), "=f"(hi) : "l"(v));
}
__device__ __forceinline__ ull fma2(ull a, ull b, ull c) {
    ull r; asm("fma.rn.f32x2 %0, %1, %2, %3;" : "=l"(r) : "l"(a), "l"(b), "l"(c)); return r;
}
__device__ __forceinline__ ull add2(ull a, ull b) {
    ull r; asm("add.rn.f32x2 %0, %1, %2;" : "=l"(r) : "l"(a), "l"(b)); return r;
}
__device__ __forceinline__ ull mul2(ull a, ull b) {
    ull r; asm("mul.rn.f32x2 %0, %1, %2;" : "=l"(r) : "l"(a), "l"(b)); return r;
}
__device__ __forceinline__ float rcpf(float a) {
    float r; asm("rcp.approx.f32 %0, %1;" : "=f"(r) : "f"(a)); return r;
}
__device__ __forceinline__ ull rcp2(ull m) {
    float a, b; unpack2(m, a, b);
    return pack2(rcpf(a), rcpf(b));
}

#define ABSM 0x7FFFFFFF7FFFFFFFULL
#define NEGM 0x8000000080000000ULL

__global__ __launch_bounds__(NTHREADS, 8)
void robust_sum_kernel(const float* __restrict__ x,
                       const float* __restrict__ w,
                       float* __restrict__ out)
{
    __shared__ float2 xs2[DIN];            // 8 KB: {x[b0][i], x[b1][i]}
    __shared__ ull red[4][32][4];          // 4 KB: [iq][lane]{q_b0,q_b1,w_b0,w_b1}

    const int tid  = threadIdx.x;
    const int iq   = tid >> 5;             // warp == i-chunk 0..3 (256 i each)
    const int lane = tid & 31;
    const int o0   = blockIdx.x * 64 + lane * 2;
    const int b0   = blockIdx.y * 2;

    // Stage x interleaved pairs (coalesced row reads).
    for (int t = tid; t < DIN; t += NTHREADS) {
        xs2[t] = make_float2(x[(size_t)b0 * DIN + t],
                             x[(size_t)(b0 + 1) * DIN + t]);
    }
    __syncthreads();

    const float2* xp    = &xs2[iq * ICHUNK];
    const float*  wbase = w + (size_t)(iq * ICHUNK) * DOUT + o0;

    // ---- pass 0: z = x @ W (as c = z/DIN), packed over (o0,o1) ----
    ull s0 = 0ULL, s1 = 0ULL;              // per-b accumulators
    #pragma unroll 4
    for (int i = 0; i < ICHUNK; i++) {
        ull wv = __ldg((const ull*)(wbase + (size_t)i * DOUT));
        float2 xv = xp[i];
        s0 = fma2(pack2(xv.x, xv.x), wv, s0);
        s1 = fma2(pack2(xv.y, xv.y), wv, s1);
    }
    red[iq][lane][0] = s0;
    red[iq][lane][1] = s1;
    __syncthreads();
    ull c0p, c1p;                          // packed c per b: (c_o0, c_o1)
    {
        ull a0 = 0ULL, a1 = 0ULL;
        #pragma unroll
        for (int j = 0; j < 4; j++) {
            a0 = add2(a0, red[j][lane][0]);
            a1 = add2(a1, red[j][lane][1]);
        }
        const ull inv = pack2(1.0f / DIN, 1.0f / DIN);
        c0p = mul2(a0, inv);
        c1p = mul2(a1, inv);
    }

    const ull EPS2 = pack2(EPSILON, EPSILON);

    // ---- K IRLS iterations: paired i (1 rcp2 per 2i per b) ----
    #pragma unroll 1
    for (int k = 0; k < KITER; k++) {
        const ull nc0 = c0p ^ NEGM;
        const ull nc1 = c1p ^ NEGM;
        ull q0 = 0ULL, q1 = 0ULL, w0 = 0ULL, w1 = 0ULL;
        #pragma unroll 4
        for (int i = 0; i < ICHUNK; i += 2) {
            ull wva = __ldg((const ull*)(wbase + (size_t)i * DOUT));
            ull wvb = __ldg((const ull*)(wbase + (size_t)(i + 1) * DOUT));
            float4 xv = *(const float4*)(xp + i);   // {x0[i],x1[i],x0[i+1],x1[i+1]}
            {   // b0: i uses xv.x, i+1 uses xv.z
                ull ta = fma2(pack2(xv.x, xv.x), wva, nc0);
                ull tb = fma2(pack2(xv.z, xv.z), wvb, nc0);
                ull da = add2(ta & ABSM, EPS2);
                ull db = add2(tb & ABSM, EPS2);
                ull r  = rcp2(mul2(da, db));
                ull cr = fma2(ta, db, mul2(tb, da));
                q0 = fma2(cr, r, q0);
                w0 = fma2(add2(da, db), r, w0);
            }
            {   // b1: i uses xv.y, i+1 uses xv.w
                ull ta = fma2(pack2(xv.y, xv.y), wva, nc1);
                ull tb = fma2(pack2(xv.w, xv.w), wvb, nc1);
                ull da = add2(ta & ABSM, EPS2);
                ull db = add2(tb & ABSM, EPS2);
                ull r  = rcp2(mul2(da, db));
                ull cr = fma2(ta, db, mul2(tb, da));
                q1 = fma2(cr, r, q1);
                w1 = fma2(add2(da, db), r, w1);
            }
        }
        __syncthreads();               // previous reduce reads done
        {
            ull* rp = red[iq][lane];
            rp[0] = q0; rp[1] = q1; rp[2] = w0; rp[3] = w1;
        }
        __syncthreads();
        ull qa = 0ULL, qb = 0ULL, wa = 0ULL, wb = 0ULL;
        #pragma unroll
        for (int j = 0; j < 4; j++) {
            const ull* rp = red[j][lane];
            qa = add2(qa, rp[0]);
            qb = add2(qb, rp[1]);
            wa = add2(wa, rp[2]);
            wb = add2(wb, rp[3]);
        }
        float qlo, qhi, wlo, whi, clo, chi;
        unpack2(c0p, clo, chi); unpack2(qa, qlo, qhi); unpack2(wa, wlo, whi);
        c0p = pack2(__fdividef(fmaf(clo, wlo, qlo), fmaxf(wlo, 1e-12f)),
                    __fdividef(fmaf(chi, whi, qhi), fmaxf(whi, 1e-12f)));
        unpack2(c1p, clo, chi); unpack2(qb, qlo, qhi); unpack2(wb, wlo, whi);
        c1p = pack2(__fdividef(fmaf(clo, wlo, qlo), fmaxf(wlo, 1e-12f)),
                    __fdividef(fmaf(chi, whi, qhi), fmaxf(whi, 1e-12f)));
    }

    if (iq == 0) {
        const float D = (float)DIN;
        float lo, hi;
        unpack2(c0p, lo, hi);
        *(float2*)(out + (size_t)(b0 + 0) * DOUT + o0) = make_float2(D * lo, D * hi);
        unpack2(c1p, lo, hi);
        *(float2*)(out + (size_t)(b0 + 1) * DOUT + o0) = make_float2(D * lo, D * hi);
    }
}

extern "C" void kernel_launch(void* const* d_in, const int* in_sizes, int n_in,
                              void* d_out, int out_size)
{
    const float* x = (const float*)d_in[0];   // (128, 1024)
    const float* w = (const float*)d_in[1];   // (1024, 1024)
    float* out = (float*)d_out;               // (128, 1024)

    dim3 grid(DOUT / 64, 128 / 2);            // (16, 64) = 1024 blocks
    robust_sum_kernel<<<grid, NTHREADS>>>(x, w, out);
}